// round 1
// baseline (speedup 1.0000x reference)
#include <cuda_runtime.h>

// Chunked Based linear attention == causal attention with kernel phi(s)=s+0.5*s^2,
// s = scale * (q . k). (The reference's chunked linear/quadratic state recurrences
// telescope exactly into the full causal sum; result is chunk_size independent.)
//
// out[b,h,c,:] = sum_{j<=c} ( s + 0.5 s^2 ) * v[j],  s = (q[c].k[j]) * D^-0.5
//
// Implementation: flash-style tiling, 64x64 q/k tiles, fp32 SIMT GEMMs,
// 256 threads/block, 4x4 microtile per thread, float4 smem fragments with
// XOR bank-group swizzle for conflict-free (<=2 phase) shared loads.

#define BB   2
#define HH   16
#define SEQ  2048
#define DD   64
#define NQT  (SEQ / 64)     // 32 query tiles per head
#define NBH  (BB * HH)      // 32 heads

// swizzled float4-chunk index for logical (row, chunk c4) in a 64x64 tile:
//   word4 = row*16 + (c4 ^ ((row>>2)&7))
__device__ __forceinline__ int swz4(int row, int c4) {
    return row * 16 + (c4 ^ ((row >> 2) & 7));
}

__global__ __launch_bounds__(256, 2)
void based_attn_kernel(const float* __restrict__ q,
                       const float* __restrict__ k,
                       const float* __restrict__ v,
                       float* __restrict__ out)
{
    __shared__ float4 sQ [64 * 16];   // Q tile  (rows = queries, cols = D), pre-scaled
    __shared__ float4 sK [64 * 16];   // K tile  (rows = keys,    cols = D); reused for phi(S)
    __shared__ float4 sVT[64 * 16];   // V tile transposed (rows = D(f), cols = keys)

    const int tid = threadIdx.x;
    const int tx  = tid & 15;         // 0..15  (output D / key col group)
    const int ty  = tid >> 4;         // 0..15  (output query row group)

    const int bh = blockIdx.y;
    const int qt = (gridDim.x - 1) - blockIdx.x;   // big q-tiles (more work) first

    const size_t head_off = (size_t)bh * SEQ * DD;
    const float* qg = q + head_off + (size_t)qt * 64 * DD;

    // ---- load Q tile (coalesced float4), pre-scaled by D^-0.5 ----
    const float scale = 0.125f;
    #pragma unroll
    for (int it = 0; it < 4; ++it) {
        int idx = tid + it * 256;          // 0..1023
        int r   = idx >> 4;                // query row 0..63
        int c4  = idx & 15;                // D chunk 0..15
        float4 val = reinterpret_cast<const float4*>(qg)[r * 16 + c4];
        val.x *= scale; val.y *= scale; val.z *= scale; val.w *= scale;
        sQ[swz4(r, c4)] = val;
    }

    float oacc[4][4] = {};   // output accumulator: rows 4ty+i, cols f=4tx+j

    for (int kt = 0; kt <= qt; ++kt) {
        __syncthreads();   // previous GEMM2 reads done (also guards Q-load on kt=0)

        // ---- load K tile and V tile (V stored transposed) ----
        const float* kg = k + head_off + (size_t)kt * 64 * DD;
        const float* vg = v + head_off + (size_t)kt * 64 * DD;
        float* sVTs = reinterpret_cast<float*>(sVT);
        #pragma unroll
        for (int it = 0; it < 4; ++it) {
            int idx = tid + it * 256;
            int r   = idx >> 4;            // key row 0..63
            int c4  = idx & 15;            // D chunk
            float4 kv = reinterpret_cast<const float4*>(kg)[r * 16 + c4];
            sK[swz4(r, c4)] = kv;
            float4 vv = reinterpret_cast<const float4*>(vg)[r * 16 + c4];
            // transpose: sVT[f][c] = V[c][f], f = 4*c4+u, c = r
            int base = (r >> 2) ^ (c4 & 7);   // swizzled chunk for col c=r at rows f0..f0+3
            int f0 = 4 * c4;
            sVTs[(f0 + 0) * 64 + (base << 2) + (r & 3)] = vv.x;
            sVTs[(f0 + 1) * 64 + (base << 2) + (r & 3)] = vv.y;
            sVTs[(f0 + 2) * 64 + (base << 2) + (r & 3)] = vv.z;
            sVTs[(f0 + 3) * 64 + (base << 2) + (r & 3)] = vv.w;
        }
        __syncthreads();

        // ---- GEMM1: S[r][c] = sum_d Qs[r][d] * K[c][d] ----
        float sacc[4][4] = {};
        #pragma unroll
        for (int cc = 0; cc < 16; ++cc) {
            float4 a[4], b[4];
            #pragma unroll
            for (int i = 0; i < 4; ++i) a[i] = sQ[(4 * ty + i) * 16 + (cc ^ (ty & 7))];
            #pragma unroll
            for (int j = 0; j < 4; ++j) b[j] = sK[(4 * tx + j) * 16 + (cc ^ (tx & 7))];
            #pragma unroll
            for (int i = 0; i < 4; ++i)
                #pragma unroll
                for (int j = 0; j < 4; ++j) {
                    sacc[i][j] = fmaf(a[i].x, b[j].x, sacc[i][j]);
                    sacc[i][j] = fmaf(a[i].y, b[j].y, sacc[i][j]);
                    sacc[i][j] = fmaf(a[i].z, b[j].z, sacc[i][j]);
                    sacc[i][j] = fmaf(a[i].w, b[j].w, sacc[i][j]);
                }
        }

        // ---- phi(s) = s + 0.5 s^2, causal mask on diagonal tile ----
        if (kt == qt) {
            #pragma unroll
            for (int i = 0; i < 4; ++i)
                #pragma unroll
                for (int j = 0; j < 4; ++j) {
                    float s = sacc[i][j];
                    float p = fmaf(0.5f * s, s, s);
                    sacc[i][j] = (4 * tx + j <= 4 * ty + i) ? p : 0.0f;
                }
        } else {
            #pragma unroll
            for (int i = 0; i < 4; ++i)
                #pragma unroll
                for (int j = 0; j < 4; ++j) {
                    float s = sacc[i][j];
                    sacc[i][j] = fmaf(0.5f * s, s, s);
                }
        }

        // ---- write phi(S) into sK buffer (K reads are done) ----
        __syncthreads();
        #pragma unroll
        for (int i = 0; i < 4; ++i) {
            float4 pv = make_float4(sacc[i][0], sacc[i][1], sacc[i][2], sacc[i][3]);
            sK[(4 * ty + i) * 16 + (tx ^ (ty & 7))] = pv;  // row = 4ty+i, chunk = tx
        }
        __syncthreads();

        // ---- GEMM2: O[r][f] += sum_c phi(S)[r][c] * V[c][f] ----
        #pragma unroll
        for (int cc = 0; cc < 16; ++cc) {
            float4 a[4], b[4];
            #pragma unroll
            for (int i = 0; i < 4; ++i) a[i] = sK [(4 * ty + i) * 16 + (cc ^ (ty & 7))];
            #pragma unroll
            for (int j = 0; j < 4; ++j) b[j] = sVT[(4 * tx + j) * 16 + (cc ^ (tx & 7))];
            #pragma unroll
            for (int i = 0; i < 4; ++i)
                #pragma unroll
                for (int j = 0; j < 4; ++j) {
                    oacc[i][j] = fmaf(a[i].x, b[j].x, oacc[i][j]);
                    oacc[i][j] = fmaf(a[i].y, b[j].y, oacc[i][j]);
                    oacc[i][j] = fmaf(a[i].z, b[j].z, oacc[i][j]);
                    oacc[i][j] = fmaf(a[i].w, b[j].w, oacc[i][j]);
                }
        }
    }

    // ---- store output tile ----
    float* og = out + head_off + (size_t)qt * 64 * DD;
    #pragma unroll
    for (int i = 0; i < 4; ++i) {
        float4 o = make_float4(oacc[i][0], oacc[i][1], oacc[i][2], oacc[i][3]);
        reinterpret_cast<float4*>(og)[(4 * ty + i) * 16 + tx] = o;
    }
}

extern "C" void kernel_launch(void* const* d_in, const int* in_sizes, int n_in,
                              void* d_out, int out_size) {
    const float* q = (const float*)d_in[0];
    const float* k = (const float*)d_in[1];
    const float* v = (const float*)d_in[2];
    // d_in[3] = chunk_size: result is chunk-size independent (telescoping cumsum), unused.
    float* out = (float*)d_out;

    dim3 grid(NQT, NBH);
    based_attn_kernel<<<grid, 256>>>(q, k, v, out);
}

// round 3
// speedup vs baseline: 2.3519x; 2.3519x over previous
#include <cuda_runtime.h>
#include <cuda_bf16.h>
#include <cstdint>

// Based linear attention == causal attention with phi(s)=s+0.5*s^2, s=scale*(q.k).
// (Reference's chunked linear+quadratic state recurrences telescope exactly.)
//
// Warp-level mma.sync (bf16, m16n8k16) flash kernel. fp32 accuracy recovered via
// split-bf16: x = hi + lo, 3 MMA passes (hi*hi + hi*lo + lo*hi), fp32 accum.
// GEMM1 C-fragments feed GEMM2 A-fragments directly in registers (no smem trip).

#define BB 2
#define HH 16
#define SEQ 2048
#define DD 64
#define QROWS 128
#define KROWS 64
#define NQT (SEQ / QROWS)   // 16
#define NBH (BB * HH)       // 32

struct SmemT {
    __nv_bfloat16 khi[64 * 64];
    __nv_bfloat16 klo[64 * 64];
    __nv_bfloat16 vhi[64 * 64];
    __nv_bfloat16 vlo[64 * 64];
};

__device__ __forceinline__ uint32_t smem_u32(const void* p) {
    uint32_t a;
    asm("{ .reg .u64 t; cvta.to.shared.u64 t, %1; cvt.u32.u64 %0, t; }" : "=r"(a) : "l"(p));
    return a;
}

// byte-offset swizzle for 128B rows: XOR row[2:0] into 16B-chunk index
__device__ __forceinline__ uint32_t swz(uint32_t b) { return b ^ ((b >> 3) & 0x70); }

__device__ __forceinline__ void mma_bf16(float* c, uint32_t a0, uint32_t a1,
                                         uint32_t a2, uint32_t a3,
                                         uint32_t b0, uint32_t b1) {
    asm volatile(
        "mma.sync.aligned.m16n8k16.row.col.f32.bf16.bf16.f32 "
        "{%0,%1,%2,%3}, {%4,%5,%6,%7}, {%8,%9}, {%0,%1,%2,%3};"
        : "+f"(c[0]), "+f"(c[1]), "+f"(c[2]), "+f"(c[3])
        : "r"(a0), "r"(a1), "r"(a2), "r"(a3), "r"(b0), "r"(b1));
}

__device__ __forceinline__ void ldsm4(uint32_t* r, uint32_t addr) {
    asm volatile("ldmatrix.sync.aligned.m8n8.x4.shared.b16 {%0,%1,%2,%3}, [%4];"
                 : "=r"(r[0]), "=r"(r[1]), "=r"(r[2]), "=r"(r[3]) : "r"(addr));
}
__device__ __forceinline__ void ldsm4t(uint32_t* r, uint32_t addr) {
    asm volatile("ldmatrix.sync.aligned.m8n8.x4.trans.shared.b16 {%0,%1,%2,%3}, [%4];"
                 : "=r"(r[0]), "=r"(r[1]), "=r"(r[2]), "=r"(r[3]) : "r"(addr));
}

// split (x,y) into packed bf16x2 hi and lo (residual) words
__device__ __forceinline__ void split2(float x, float y, uint32_t& hi, uint32_t& lo) {
    __nv_bfloat162 h = __floats2bfloat162_rn(x, y);
    float2 hf = __bfloat1622float2(h);
    __nv_bfloat162 l = __floats2bfloat162_rn(x - hf.x, y - hf.y);
    hi = *reinterpret_cast<uint32_t*>(&h);
    lo = *reinterpret_cast<uint32_t*>(&l);
}

__global__ __launch_bounds__(256, 2)
void based_mma_kernel(const float* __restrict__ q, const float* __restrict__ k,
                      const float* __restrict__ v, float* __restrict__ out)
{
    __shared__ SmemT sm;

    const int tid  = threadIdx.x;
    const int lane = tid & 31;
    const int w    = tid >> 5;          // warp 0..7, owns q-rows [16w,16w+16)
    const int g    = lane >> 2;         // group row 0..7
    const int t4   = lane & 3;

    const int bh = blockIdx.y;
    const int qt = (NQT - 1) - blockIdx.x;   // big q-tiles first
    const size_t head = (size_t)bh * SEQ * DD;

    // ---- Q fragments: register-resident for the whole CTA lifetime ----
    // qh/ql[kb][h]: A-frag (16x16 block kb of D) regs h: 0:(r,c) 1:(r+8,c) 2:(r,c+8) 3:(r+8,c+8)
    uint32_t qh[4][4], ql[4][4];
    const int r0 = qt * QROWS + w * 16 + g;
    {
        const float scale = 0.125f;
        const float* qb = q + head;
        #pragma unroll
        for (int kb = 0; kb < 4; ++kb)
            #pragma unroll
            for (int h = 0; h < 4; ++h) {
                int row = r0 + ((h & 1) ? 8 : 0);
                int col = kb * 16 + t4 * 2 + ((h & 2) ? 8 : 0);
                float2 val = *reinterpret_cast<const float2*>(qb + (size_t)row * DD + col);
                split2(val.x * scale, val.y * scale, qh[kb][h], ql[kb][h]);
            }
    }

    float oacc[8][4] = {};   // O frag: nb over 8-col blocks of D

    const uint32_t kh_b = smem_u32(sm.khi), kl_b = smem_u32(sm.klo);
    const uint32_t vh_b = smem_u32(sm.vhi), vl_b = smem_u32(sm.vlo);
    const uint32_t sw = (lane & 7) << 4;
    const int rowK = ((lane >> 3) & 1) * 8 + (lane & 7);   // GEMM1 B ldmatrix row part
    const int colK = (lane >> 4) * 16;
    const int rowV = ((lane >> 4) & 1) * 8 + (lane & 7);   // GEMM2 B (trans) row part
    const int colV = ((lane >> 3) & 1) * 16;

    const int nkt = 2 * qt + 2;
    for (int kt = 0; kt < nkt; ++kt) {
        if (kt) __syncthreads();   // prior ldmatrix reads done before overwrite

        // ---- convert K, V tiles (64x64 fp32 -> bf16 hi/lo), swizzled ----
        const float* kg = k + head + (size_t)kt * KROWS * DD;
        const float* vg = v + head + (size_t)kt * KROWS * DD;
        #pragma unroll
        for (int it = 0; it < 4; ++it) {
            int idx = tid + it * 256;       // 0..1023 float4-chunks
            int r = idx >> 4, c4 = idx & 15;
            uint32_t so = swz((uint32_t)(r * 128 + c4 * 8));

            float4 kv = reinterpret_cast<const float4*>(kg)[idx];
            uint32_t h0, l0, h1, l1;
            split2(kv.x, kv.y, h0, l0);
            split2(kv.z, kv.w, h1, l1);
            *reinterpret_cast<uint2*>((char*)sm.khi + so) = make_uint2(h0, h1);
            *reinterpret_cast<uint2*>((char*)sm.klo + so) = make_uint2(l0, l1);

            float4 vv = reinterpret_cast<const float4*>(vg)[idx];
            split2(vv.x, vv.y, h0, l0);
            split2(vv.z, vv.w, h1, l1);
            *reinterpret_cast<uint2*>((char*)sm.vhi + so) = make_uint2(h0, h1);
            *reinterpret_cast<uint2*>((char*)sm.vlo + so) = make_uint2(l0, l1);
        }
        __syncthreads();

        // ---- GEMM1: S[16x64] = Q_w * K^T  (3 split passes fused per B load) ----
        float sacc[8][4] = {};
        #pragma unroll
        for (int kk = 0; kk < 4; ++kk) {
            #pragma unroll
            for (int p = 0; p < 4; ++p) {
                uint32_t off = (uint32_t)((16 * p + rowK) * 128) + (((uint32_t)(32 * kk + colK)) ^ sw);
                uint32_t bhr[4], blr[4];
                ldsm4(bhr, kh_b + off);
                ldsm4(blr, kl_b + off);
                // nb = 2p (B regs {0,2}) and 2p+1 ({1,3}), interleaved for ILP
                mma_bf16(sacc[2*p],   qh[kk][0],qh[kk][1],qh[kk][2],qh[kk][3], bhr[0], bhr[2]);
                mma_bf16(sacc[2*p+1], qh[kk][0],qh[kk][1],qh[kk][2],qh[kk][3], bhr[1], bhr[3]);
                mma_bf16(sacc[2*p],   qh[kk][0],qh[kk][1],qh[kk][2],qh[kk][3], blr[0], blr[2]);
                mma_bf16(sacc[2*p+1], qh[kk][0],qh[kk][1],qh[kk][2],qh[kk][3], blr[1], blr[3]);
                mma_bf16(sacc[2*p],   ql[kk][0],ql[kk][1],ql[kk][2],ql[kk][3], bhr[0], bhr[2]);
                mma_bf16(sacc[2*p+1], ql[kk][0],ql[kk][1],ql[kk][2],ql[kk][3], bhr[1], bhr[3]);
            }
        }

        // ---- phi(s)=s+0.5s^2, causal mask, split into GEMM2 A-fragments ----
        uint32_t ah[4][4], al[4][4];
        const bool edge = (kt >= 2 * qt);
        #pragma unroll
        for (int nb = 0; nb < 8; ++nb) {
            int colg = kt * KROWS + nb * 8 + 2 * t4;
            float e[4];
            #pragma unroll
            for (int u = 0; u < 4; ++u) {
                float s = sacc[nb][u];
                float p = fmaf(0.5f * s, s, s);
                if (edge && (colg + (u & 1) > r0 + ((u & 2) ? 8 : 0))) p = 0.0f;
                e[u] = p;
            }
            int kk = nb >> 1, half = (nb & 1) * 2;
            split2(e[0], e[1], ah[kk][half],     al[kk][half]);
            split2(e[2], e[3], ah[kk][half + 1], al[kk][half + 1]);
        }

        // ---- GEMM2: O += phi(S) * V  (V via ldmatrix.trans) ----
        #pragma unroll
        for (int kk = 0; kk < 4; ++kk) {
            #pragma unroll
            for (int p = 0; p < 4; ++p) {
                uint32_t off = (uint32_t)((16 * kk + rowV) * 128) + (((uint32_t)(32 * p + colV)) ^ sw);
                uint32_t vhr[4], vlr[4];
                ldsm4t(vhr, vh_b + off);
                ldsm4t(vlr, vl_b + off);
                mma_bf16(oacc[2*p],   ah[kk][0],ah[kk][1],ah[kk][2],ah[kk][3], vhr[0], vhr[2]);
                mma_bf16(oacc[2*p+1], ah[kk][0],ah[kk][1],ah[kk][2],ah[kk][3], vhr[1], vhr[3]);
                mma_bf16(oacc[2*p],   ah[kk][0],ah[kk][1],ah[kk][2],ah[kk][3], vlr[0], vlr[2]);
                mma_bf16(oacc[2*p+1], ah[kk][0],ah[kk][1],ah[kk][2],ah[kk][3], vlr[1], vlr[3]);
                mma_bf16(oacc[2*p],   al[kk][0],al[kk][1],al[kk][2],al[kk][3], vhr[0], vhr[2]);
                mma_bf16(oacc[2*p+1], al[kk][0],al[kk][1],al[kk][2],al[kk][3], vhr[1], vhr[3]);
            }
        }
    }

    // ---- store O fragments ----
    float* og = out + head;
    #pragma unroll
    for (int nb = 0; nb < 8; ++nb) {
        int col = nb * 8 + 2 * t4;
        *reinterpret_cast<float2*>(og + (size_t)r0 * DD + col) =
            make_float2(oacc[nb][0], oacc[nb][1]);
        *reinterpret_cast<float2*>(og + (size_t)(r0 + 8) * DD + col) =
            make_float2(oacc[nb][2], oacc[nb][3]);
    }
}

extern "C" void kernel_launch(void* const* d_in, const int* in_sizes, int n_in,
                              void* d_out, int out_size) {
    const float* q = (const float*)d_in[0];
    const float* k = (const float*)d_in[1];
    const float* v = (const float*)d_in[2];
    float* out = (float*)d_out;

    dim3 grid(NQT, NBH);
    based_mma_kernel<<<grid, 256>>>(q, k, v, out);
}